// round 12
// baseline (speedup 1.0000x reference)
#include <cuda_runtime.h>
#include <cuda_bf16.h>

typedef unsigned long long u64;

#define NLEVELS 16
#define TSIZE   (1u << 19)
#define HIDDEN  32
#define NPTS_MAX 2000000
#define CELL_BITS 7
#define CELLS_AXIS (1 << CELL_BITS)
#define NCELLS (1u << (3 * CELL_BITS))
#define SCAN_BLK 1024
#define NPART (NCELLS / SCAN_BLK)

#define NTILED 11
#define TILE_TOTAL 2192

// ---- static scratch ----
__device__ unsigned g_cell_count[NCELLS];
__device__ unsigned g_cell_start[NCELLS];
__device__ unsigned g_partials[NPART];
__device__ float4   g_pts[NPTS_MAX];

__constant__ float c_scales[NLEVELS] = {
    15.0f, 19.158736798317971f, 24.398416831491190f, 31.0f,
    39.317473596635942f, 49.796833662982379f, 63.0f, 79.634947193271885f,
    100.59366732596476f, 127.0f, 160.26989438654377f, 202.18733465192952f,
    255.0f, 321.53978877308754f, 405.37466930385904f, 511.0f
};

__constant__ int c_cap[NTILED] = {32, 32, 48, 64, 96, 128, 160, 224, 320, 448, 640};
__constant__ int c_off[NTILED] = {0, 32, 64, 112, 176, 272, 400, 560, 784, 1104, 1552};

// ---- packed f32x2 helpers ----
__device__ __forceinline__ u64 pack2(float lo, float hi) {
    u64 r; asm("mov.b64 %0, {%1, %2};" : "=l"(r) : "f"(lo), "f"(hi)); return r;
}
__device__ __forceinline__ void unpack2(u64 v, float& lo, float& hi) {
    asm("mov.b64 {%0, %1}, %2;" : "=f"(lo), "=f"(hi) : "l"(v));
}
__device__ __forceinline__ u64 ffma2(u64 a, u64 b, u64 c) {
    u64 d; asm("fma.rn.f32x2 %0, %1, %2, %3;" : "=l"(d) : "l"(a), "l"(b), "l"(c)); return d;
}

__device__ __forceinline__ unsigned expand3(unsigned v) {
    v &= 0x3FFu;
    v = (v | (v << 16)) & 0x030000FFu;
    v = (v | (v << 8))  & 0x0300F00Fu;
    v = (v | (v << 4))  & 0x030C30C3u;
    v = (v | (v << 2))  & 0x09249249u;
    return v;
}

__device__ __forceinline__ unsigned cell_code(float xn0, float xn1, float xn2) {
    int c0 = min(CELLS_AXIS - 1, max(0, (int)(xn0 * (float)CELLS_AXIS)));
    int c1 = min(CELLS_AXIS - 1, max(0, (int)(xn1 * (float)CELLS_AXIS)));
    int c2 = min(CELLS_AXIS - 1, max(0, (int)(xn2 * (float)CELLS_AXIS)));
    return expand3((unsigned)c0) | (expand3((unsigned)c1) << 1) | (expand3((unsigned)c2) << 2);
}

// ---- sort pipeline ----
__global__ void zero_counts_kernel() {
    unsigned i = blockIdx.x * blockDim.x + threadIdx.x;
    reinterpret_cast<uint4*>(g_cell_count)[i] = make_uint4(0u, 0u, 0u, 0u);
}

__global__ void hist_kernel(const float* __restrict__ x, int n) {
    int i = blockIdx.x * blockDim.x + threadIdx.x;
    if (i >= n) return;
    const float xn0 = (x[3 * i + 0] + 1.0f) * 0.5f;
    const float xn1 = (x[3 * i + 1] + 1.0f) * 0.5f;
    const float xn2 = (x[3 * i + 2] + 1.0f) * 0.5f;
    atomicAdd(&g_cell_count[cell_code(xn0, xn1, xn2)], 1u);
}

__device__ __forceinline__ unsigned block_incl_scan(unsigned v, unsigned tid) {
    __shared__ unsigned warp_sums[32];
    unsigned inc = v;
    #pragma unroll
    for (int off = 1; off < 32; off <<= 1) {
        unsigned t = __shfl_up_sync(~0u, inc, off);
        if ((tid & 31u) >= (unsigned)off) inc += t;
    }
    if ((tid & 31u) == 31u) warp_sums[tid >> 5] = inc;
    __syncthreads();
    if (tid < 32) {
        unsigned s = warp_sums[tid];
        #pragma unroll
        for (int off = 1; off < 32; off <<= 1) {
            unsigned t = __shfl_up_sync(~0u, s, off);
            if (tid >= (unsigned)off) s += t;
        }
        warp_sums[tid] = s;
    }
    __syncthreads();
    unsigned base = (tid >= 32u) ? warp_sums[(tid >> 5) - 1u] : 0u;
    return base + inc;
}

__global__ void scan1_kernel() {
    const unsigned tid = threadIdx.x;
    const unsigned g = blockIdx.x * SCAN_BLK + tid;
    const unsigned v = g_cell_count[g];
    const unsigned inc = block_incl_scan(v, tid);
    g_cell_start[g] = inc - v;
    if (tid == SCAN_BLK - 1) g_partials[blockIdx.x] = inc;
}

__global__ void scan2_kernel() {
    const unsigned tid = threadIdx.x;
    const unsigned a = g_partials[2 * tid];
    const unsigned b = g_partials[2 * tid + 1];
    const unsigned s = a + b;
    const unsigned inc = block_incl_scan(s, tid);
    const unsigned excl = inc - s;
    g_partials[2 * tid]     = excl;
    g_partials[2 * tid + 1] = excl + a;
}

// scatter adds the block offset itself (scan3 folded in)
__global__ void scatter_kernel(const float* __restrict__ x, int n) {
    int i = blockIdx.x * blockDim.x + threadIdx.x;
    if (i >= n) return;
    const float xn0 = (x[3 * i + 0] + 1.0f) * 0.5f;
    const float xn1 = (x[3 * i + 1] + 1.0f) * 0.5f;
    const float xn2 = (x[3 * i + 2] + 1.0f) * 0.5f;
    const unsigned c = cell_code(xn0, xn1, xn2);
    const unsigned pos = atomicAdd(&g_cell_start[c], 1u) + g_partials[c >> 10];
    g_pts[pos] = make_float4(xn0, xn1, xn2, __uint_as_float((unsigned)i));
}

// ---- fused hash-encode + MLP: per-block smem tiles for levels 0..10,
//      2 points/thread block-strided, packed f32x2 ----
__global__ __launch_bounds__(128)
void field_fused_kernel(const float* __restrict__ table,
                        const float* __restrict__ W0,
                        const float* __restrict__ b0,
                        const float* __restrict__ W1,
                        const float* __restrict__ b1,
                        const float* __restrict__ Wout,
                        const float* __restrict__ bout,
                        float* __restrict__ out,
                        int n)
{
    __shared__ u64 sW0[35 * 32];
    __shared__ u64 sW1[32 * 32];
    __shared__ u64 sb0[32];
    __shared__ u64 sb1[32];
    __shared__ u64 sWout[32];
    __shared__ float sbout;
    __shared__ unsigned sbb[6];                 // bbox min(0..2) / max(3..5), uint-punned
    __shared__ unsigned sB0[NTILED], sB1[NTILED], sB2[NTILED];
    __shared__ int sDx[NTILED], sDxdy[NTILED], sE[NTILED], sFit[NTILED];
    __shared__ float2 sTile[TILE_TOTAL];

    const int tid = threadIdx.x;
    for (int i = tid; i < 35 * 32; i += blockDim.x) { float w = W0[i]; sW0[i] = pack2(w, w); }
    for (int i = tid; i < 32 * 32; i += blockDim.x) { float w = W1[i]; sW1[i] = pack2(w, w); }
    if (tid < 32) {
        float v0 = b0[tid];   sb0[tid]   = pack2(v0, v0);
        float v1 = b1[tid];   sb1[tid]   = pack2(v1, v1);
        float vo = Wout[tid]; sWout[tid] = pack2(vo, vo);
    }
    if (tid == 0) sbout = bout[0];
    if (tid < 3) sbb[tid] = 0x7F800000u;        // +inf
    if (tid >= 3 && tid < 6) sbb[tid] = 0u;
    __syncthreads();

    // block-strided pairing over a 256-point chunk
    const int base = blockIdx.x * 256;
    const int iAr = base + tid;
    const bool validA = iAr < n;
    const int iA = validA ? iAr : (n - 1);
    const int iBr = base + 128 + tid;
    const bool hasB = iBr < n;
    const int iB = hasB ? iBr : iA;

    const float4 ptA = g_pts[iA];
    const float4 ptB = g_pts[iB];
    const unsigned oiA = __float_as_uint(ptA.w);
    const unsigned oiB = __float_as_uint(ptB.w);

    // bbox over block's points (positive floats: uint order == float order)
    atomicMin(&sbb[0], __float_as_uint(ptA.x));
    atomicMin(&sbb[1], __float_as_uint(ptA.y));
    atomicMin(&sbb[2], __float_as_uint(ptA.z));
    atomicMax(&sbb[3], __float_as_uint(ptA.x));
    atomicMax(&sbb[4], __float_as_uint(ptA.y));
    atomicMax(&sbb[5], __float_as_uint(ptA.z));
    atomicMin(&sbb[0], __float_as_uint(ptB.x));
    atomicMin(&sbb[1], __float_as_uint(ptB.y));
    atomicMin(&sbb[2], __float_as_uint(ptB.z));
    atomicMax(&sbb[3], __float_as_uint(ptB.x));
    atomicMax(&sbb[4], __float_as_uint(ptB.y));
    atomicMax(&sbb[5], __float_as_uint(ptB.z));
    __syncthreads();

    // per-level tile metadata (one thread per tiled level)
    if (tid < NTILED) {
        const float s = c_scales[tid];
        const float bn0 = __uint_as_float(sbb[0]) * s;
        const float bn1 = __uint_as_float(sbb[1]) * s;
        const float bn2 = __uint_as_float(sbb[2]) * s;
        const float bx0 = __uint_as_float(sbb[3]) * s;
        const float bx1 = __uint_as_float(sbb[4]) * s;
        const float bx2 = __uint_as_float(sbb[5]) * s;
        const unsigned b0i = (unsigned)floorf(bn0);
        const unsigned b1i = (unsigned)floorf(bn1);
        const unsigned b2i = (unsigned)floorf(bn2);
        const int dx = (int)((unsigned)floorf(bx0) - b0i) + 2;
        const int dy = (int)((unsigned)floorf(bx1) - b1i) + 2;
        const int dz = (int)((unsigned)floorf(bx2) - b2i) + 2;
        const int E = dx * dy * dz;
        sB0[tid] = b0i; sB1[tid] = b1i; sB2[tid] = b2i;
        sDx[tid] = dx; sDxdy[tid] = dx * dy; sE[tid] = E;
        sFit[tid] = (E <= c_cap[tid]) ? 1 : 0;
    }
    __syncthreads();

    // build tiles (cooperative gather of distinct entries)
    #pragma unroll 1
    for (int l = 0; l < NTILED; l++) {
        if (!sFit[l]) continue;
        const int E = sE[l], dx = sDx[l], dxdy = sDxdy[l];
        const unsigned b0i = sB0[l], b1i = sB1[l], b2i = sB2[l];
        const int off = c_off[l];
        const float2* __restrict__ tbl =
            reinterpret_cast<const float2*>(table) + (size_t)l * TSIZE;
        for (int e = tid; e < E; e += 128) {
            const int w = e / dxdy;
            const int r = e - w * dxdy;
            const int v = r / dx;
            const int u = r - v * dx;
            const unsigned hx = b0i + (unsigned)u;
            const unsigned hy = (b1i + (unsigned)v) * 2654435761u;
            const unsigned hz = (b2i + (unsigned)w) * 805459861u;
            sTile[off + e] = __ldg(tbl + ((hx ^ hy ^ hz) & (TSIZE - 1u)));
        }
    }
    __syncthreads();

    const u64 xp0 = pack2(ptA.x, ptB.x);
    const u64 xp1 = pack2(ptA.y, ptB.y);
    const u64 xp2 = pack2(ptA.z, ptB.z);

    u64 h[HIDDEN];
    #pragma unroll
    for (int j = 0; j < HIDDEN; j++) {
        h[j] = ffma2(xp0, sW0[0 * 32 + j],
               ffma2(xp1, sW0[1 * 32 + j],
               ffma2(xp2, sW0[2 * 32 + j], sb0[j])));
    }

    // ---- levels 0..10: tiled (LDS) with direct-LDG fallback ----
    #pragma unroll 1
    for (int l = 0; l < NTILED; l++) {
        const float s = c_scales[l];
        const float2* __restrict__ tbl =
            reinterpret_cast<const float2*>(table) + (size_t)l * TSIZE;

        const float pA0 = ptA.x * s, pA1 = ptA.y * s, pA2 = ptA.z * s;
        const float fA0 = floorf(pA0), fA1 = floorf(pA1), fA2 = floorf(pA2);
        const float wA0 = pA0 - fA0, wA1 = pA1 - fA1, wA2 = pA2 - fA2;
        const unsigned iA0 = (unsigned)fA0, iA1 = (unsigned)fA1, iA2 = (unsigned)fA2;

        const float pB0 = ptB.x * s, pB1 = ptB.y * s, pB2 = ptB.z * s;
        const float fB0 = floorf(pB0), fB1 = floorf(pB1), fB2 = floorf(pB2);
        const float wB0 = pB0 - fB0, wB1 = pB1 - fB1, wB2 = pB2 - fB2;
        const unsigned iB0 = (unsigned)fB0, iB1 = (unsigned)fB1, iB2 = (unsigned)fB2;

        u64 a0 = 0ull, a1 = 0ull;
        if (sFit[l]) {
            const int dx = sDx[l], dxdy = sDxdy[l];
            const float2* __restrict__ tile = &sTile[c_off[l]];
            const int bA = (int)(iA0 - sB0[l]) + dx * (int)(iA1 - sB1[l]) + dxdy * (int)(iA2 - sB2[l]);
            const int bB = (int)(iB0 - sB0[l]) + dx * (int)(iB1 - sB1[l]) + dxdy * (int)(iB2 - sB2[l]);
            #pragma unroll
            for (int c = 0; c < 8; c++) {
                const int dlt = (c & 1) + ((c & 2) ? dx : 0) + ((c & 4) ? dxdy : 0);
                const float2 gA = tile[bA + dlt];
                const float2 gB = tile[bB + dlt];
                const float wtA = ((c & 1) ? wA0 : 1.0f - wA0)
                                * ((c & 2) ? wA1 : 1.0f - wA1)
                                * ((c & 4) ? wA2 : 1.0f - wA2);
                const float wtB = ((c & 1) ? wB0 : 1.0f - wB0)
                                * ((c & 2) ? wB1 : 1.0f - wB1)
                                * ((c & 4) ? wB2 : 1.0f - wB2);
                const u64 wtp = pack2(wtA, wtB);
                a0 = ffma2(wtp, pack2(gA.x, gB.x), a0);
                a1 = ffma2(wtp, pack2(gA.y, gB.y), a1);
            }
        } else {
            const unsigned hxA0 = iA0,               hxA1 = iA0 + 1u;
            const unsigned hyA0 = iA1 * 2654435761u, hyA1 = (iA1 + 1u) * 2654435761u;
            const unsigned hzA0 = iA2 * 805459861u,  hzA1 = (iA2 + 1u) * 805459861u;
            const unsigned hxB0 = iB0,               hxB1 = iB0 + 1u;
            const unsigned hyB0 = iB1 * 2654435761u, hyB1 = (iB1 + 1u) * 2654435761u;
            const unsigned hzB0 = iB2 * 805459861u,  hzB1 = (iB2 + 1u) * 805459861u;
            #pragma unroll
            for (int c = 0; c < 8; c++) {
                const unsigned idxA = (((c & 1) ? hxA1 : hxA0) ^ ((c & 2) ? hyA1 : hyA0)
                                     ^ ((c & 4) ? hzA1 : hzA0)) & (TSIZE - 1u);
                const unsigned idxB = (((c & 1) ? hxB1 : hxB0) ^ ((c & 2) ? hyB1 : hyB0)
                                     ^ ((c & 4) ? hzB1 : hzB0)) & (TSIZE - 1u);
                const float wtA = ((c & 1) ? wA0 : 1.0f - wA0)
                                * ((c & 2) ? wA1 : 1.0f - wA1)
                                * ((c & 4) ? wA2 : 1.0f - wA2);
                const float wtB = ((c & 1) ? wB0 : 1.0f - wB0)
                                * ((c & 2) ? wB1 : 1.0f - wB1)
                                * ((c & 4) ? wB2 : 1.0f - wB2);
                const float2 gA = __ldg(tbl + idxA);
                const float2 gB = __ldg(tbl + idxB);
                const u64 wtp = pack2(wtA, wtB);
                a0 = ffma2(wtp, pack2(gA.x, gB.x), a0);
                a1 = ffma2(wtp, pack2(gA.y, gB.y), a1);
            }
        }

        const u64* wr0 = &sW0[(3 + 2 * l) * 32];
        const u64* wr1 = &sW0[(4 + 2 * l) * 32];
        #pragma unroll
        for (int j = 0; j < HIDDEN; j++) {
            h[j] = ffma2(a0, wr0[j], ffma2(a1, wr1[j], h[j]));
        }
    }

    // ---- levels 11..15: direct gathers ----
    #pragma unroll 1
    for (int l = NTILED; l < NLEVELS; l++) {
        const float s = c_scales[l];
        const float2* __restrict__ tbl =
            reinterpret_cast<const float2*>(table) + (size_t)l * TSIZE;

        const float pA0 = ptA.x * s, pA1 = ptA.y * s, pA2 = ptA.z * s;
        const float fA0 = floorf(pA0), fA1 = floorf(pA1), fA2 = floorf(pA2);
        const float wA0 = pA0 - fA0, wA1 = pA1 - fA1, wA2 = pA2 - fA2;
        const unsigned iA0 = (unsigned)fA0, iA1 = (unsigned)fA1, iA2 = (unsigned)fA2;
        const unsigned hxA0 = iA0,               hxA1 = iA0 + 1u;
        const unsigned hyA0 = iA1 * 2654435761u, hyA1 = (iA1 + 1u) * 2654435761u;
        const unsigned hzA0 = iA2 * 805459861u,  hzA1 = (iA2 + 1u) * 805459861u;

        const float pB0 = ptB.x * s, pB1 = ptB.y * s, pB2 = ptB.z * s;
        const float fB0 = floorf(pB0), fB1 = floorf(pB1), fB2 = floorf(pB2);
        const float wB0 = pB0 - fB0, wB1 = pB1 - fB1, wB2 = pB2 - fB2;
        const unsigned iB0 = (unsigned)fB0, iB1 = (unsigned)fB1, iB2 = (unsigned)fB2;
        const unsigned hxB0 = iB0,               hxB1 = iB0 + 1u;
        const unsigned hyB0 = iB1 * 2654435761u, hyB1 = (iB1 + 1u) * 2654435761u;
        const unsigned hzB0 = iB2 * 805459861u,  hzB1 = (iB2 + 1u) * 805459861u;

        u64 a0 = 0ull, a1 = 0ull;
        #pragma unroll
        for (int c = 0; c < 8; c++) {
            const unsigned idxA = (((c & 1) ? hxA1 : hxA0) ^ ((c & 2) ? hyA1 : hyA0)
                                 ^ ((c & 4) ? hzA1 : hzA0)) & (TSIZE - 1u);
            const unsigned idxB = (((c & 1) ? hxB1 : hxB0) ^ ((c & 2) ? hyB1 : hyB0)
                                 ^ ((c & 4) ? hzB1 : hzB0)) & (TSIZE - 1u);
            const float wtA = ((c & 1) ? wA0 : 1.0f - wA0)
                            * ((c & 2) ? wA1 : 1.0f - wA1)
                            * ((c & 4) ? wA2 : 1.0f - wA2);
            const float wtB = ((c & 1) ? wB0 : 1.0f - wB0)
                            * ((c & 2) ? wB1 : 1.0f - wB1)
                            * ((c & 4) ? wB2 : 1.0f - wB2);
            const float2 gA = __ldg(tbl + idxA);
            const float2 gB = __ldg(tbl + idxB);
            const u64 wtp = pack2(wtA, wtB);
            a0 = ffma2(wtp, pack2(gA.x, gB.x), a0);
            a1 = ffma2(wtp, pack2(gA.y, gB.y), a1);
        }

        const u64* wr0 = &sW0[(3 + 2 * l) * 32];
        const u64* wr1 = &sW0[(4 + 2 * l) * 32];
        #pragma unroll
        for (int j = 0; j < HIDDEN; j++) {
            h[j] = ffma2(a0, wr0[j], ffma2(a1, wr1[j], h[j]));
        }
    }

    // ---- ELU ----
    #pragma unroll
    for (int j = 0; j < HIDDEN; j++) {
        float a, b;
        unpack2(h[j], a, b);
        a = a > 0.0f ? a : expm1f(a);
        b = b > 0.0f ? b : expm1f(b);
        h[j] = pack2(a, b);
    }

    // ---- layer 1 + output ----
    u64 o = pack2(sbout, sbout);
    #pragma unroll 4
    for (int j = 0; j < HIDDEN; j++) {
        u64 t = sb1[j];
        #pragma unroll
        for (int i = 0; i < HIDDEN; i++) {
            t = ffma2(h[i], sW1[i * 32 + j], t);
        }
        float a, b;
        unpack2(t, a, b);
        a = a > 0.0f ? a : expm1f(a);
        b = b > 0.0f ? b : expm1f(b);
        o = ffma2(pack2(a, b), sWout[j], o);
    }

    float oA, oB;
    unpack2(o, oA, oB);
    if (validA) out[oiA] = oA;
    if (hasB)   out[oiB] = oB;
}

extern "C" void kernel_launch(void* const* d_in, const int* in_sizes, int n_in,
                              void* d_out, int out_size)
{
    const float* x     = (const float*)d_in[0];
    const float* table = (const float*)d_in[1];
    const float* W0    = (const float*)d_in[2];
    const float* b0    = (const float*)d_in[3];
    const float* W1    = (const float*)d_in[4];
    const float* b1    = (const float*)d_in[5];
    const float* Wout  = (const float*)d_in[6];
    const float* bout  = (const float*)d_in[7];
    float* out = (float*)d_out;

    const int n = in_sizes[0] / 3;

    zero_counts_kernel<<<NCELLS / 4 / 1024, 1024>>>();
    hist_kernel<<<(n + 255) / 256, 256>>>(x, n);
    scan1_kernel<<<NPART, SCAN_BLK>>>();
    scan2_kernel<<<1, SCAN_BLK>>>();
    scatter_kernel<<<(n + 255) / 256, 256>>>(x, n);

    const int nchunk = (n + 255) / 256;
    field_fused_kernel<<<nchunk, 128>>>(
        table, W0, b0, W1, b1, Wout, bout, out, n);
}

// round 13
// speedup vs baseline: 1.2543x; 1.2543x over previous
#include <cuda_runtime.h>
#include <cuda_bf16.h>

typedef unsigned long long u64;

#define NLEVELS 16
#define TSIZE   (1u << 19)
#define HIDDEN  32
#define NPTS_MAX 2000000
#define CELL_BITS 7
#define CELLS_AXIS (1 << CELL_BITS)
#define NCELLS (1u << (3 * CELL_BITS))
#define SCAN_BLK 1024
#define NPART (NCELLS / SCAN_BLK)

// ---- static scratch ----
__device__ unsigned g_cell_count[NCELLS];
__device__ unsigned g_cell_start[NCELLS];
__device__ unsigned g_partials[NPART];
__device__ float4   g_pts[NPTS_MAX];

__constant__ float c_scales[NLEVELS] = {
    15.0f, 19.158736798317971f, 24.398416831491190f, 31.0f,
    39.317473596635942f, 49.796833662982379f, 63.0f, 79.634947193271885f,
    100.59366732596476f, 127.0f, 160.26989438654377f, 202.18733465192952f,
    255.0f, 321.53978877308754f, 405.37466930385904f, 511.0f
};

// ---- packed f32x2 helpers ----
__device__ __forceinline__ u64 pack2(float lo, float hi) {
    u64 r; asm("mov.b64 %0, {%1, %2};" : "=l"(r) : "f"(lo), "f"(hi)); return r;
}
__device__ __forceinline__ void unpack2(u64 v, float& lo, float& hi) {
    asm("mov.b64 {%0, %1}, %2;" : "=f"(lo), "=f"(hi) : "l"(v));
}
__device__ __forceinline__ u64 ffma2(u64 a, u64 b, u64 c) {
    u64 d; asm("fma.rn.f32x2 %0, %1, %2, %3;" : "=l"(d) : "l"(a), "l"(b), "l"(c)); return d;
}
__device__ __forceinline__ u64 fmul2(u64 a, u64 b) {
    u64 d; asm("mul.rn.f32x2 %0, %1, %2;" : "=l"(d) : "l"(a), "l"(b)); return d;
}

__device__ __forceinline__ float elu_fast(float v) {
    float e = __expf(v) - 1.0f;
    return v > 0.0f ? v : e;
}

__device__ __forceinline__ unsigned expand3(unsigned v) {
    v &= 0x3FFu;
    v = (v | (v << 16)) & 0x030000FFu;
    v = (v | (v << 8))  & 0x0300F00Fu;
    v = (v | (v << 4))  & 0x030C30C3u;
    v = (v | (v << 2))  & 0x09249249u;
    return v;
}

__device__ __forceinline__ unsigned cell_code(float xn0, float xn1, float xn2) {
    int c0 = min(CELLS_AXIS - 1, max(0, (int)(xn0 * (float)CELLS_AXIS)));
    int c1 = min(CELLS_AXIS - 1, max(0, (int)(xn1 * (float)CELLS_AXIS)));
    int c2 = min(CELLS_AXIS - 1, max(0, (int)(xn2 * (float)CELLS_AXIS)));
    return expand3((unsigned)c0) | (expand3((unsigned)c1) << 1) | (expand3((unsigned)c2) << 2);
}

// ---- sort pipeline ----
__global__ void zero_counts_kernel() {
    unsigned i = blockIdx.x * blockDim.x + threadIdx.x;
    reinterpret_cast<uint4*>(g_cell_count)[i] = make_uint4(0u, 0u, 0u, 0u);
}

// 4 points per thread, float4-coalesced input reads
__global__ void hist_kernel(const float* __restrict__ x, int n) {
    const int j = blockIdx.x * blockDim.x + threadIdx.x;
    const int p0 = j * 4;
    if (p0 >= n) return;
    float c[12];
    if (p0 + 3 < n) {
        const float4* __restrict__ x4 = reinterpret_cast<const float4*>(x);
        const float4 a = x4[3 * j], b = x4[3 * j + 1], d = x4[3 * j + 2];
        c[0]=a.x; c[1]=a.y; c[2]=a.z; c[3]=a.w; c[4]=b.x; c[5]=b.y;
        c[6]=b.z; c[7]=b.w; c[8]=d.x; c[9]=d.y; c[10]=d.z; c[11]=d.w;
        #pragma unroll
        for (int k = 0; k < 4; k++) {
            const float xn0 = (c[3*k+0] + 1.0f) * 0.5f;
            const float xn1 = (c[3*k+1] + 1.0f) * 0.5f;
            const float xn2 = (c[3*k+2] + 1.0f) * 0.5f;
            atomicAdd(&g_cell_count[cell_code(xn0, xn1, xn2)], 1u);
        }
    } else {
        for (int k = 0; k < 4 && p0 + k < n; k++) {
            const int i = p0 + k;
            const float xn0 = (x[3*i+0] + 1.0f) * 0.5f;
            const float xn1 = (x[3*i+1] + 1.0f) * 0.5f;
            const float xn2 = (x[3*i+2] + 1.0f) * 0.5f;
            atomicAdd(&g_cell_count[cell_code(xn0, xn1, xn2)], 1u);
        }
    }
}

__device__ __forceinline__ unsigned block_incl_scan(unsigned v, unsigned tid) {
    __shared__ unsigned warp_sums[32];
    unsigned inc = v;
    #pragma unroll
    for (int off = 1; off < 32; off <<= 1) {
        unsigned t = __shfl_up_sync(~0u, inc, off);
        if ((tid & 31u) >= (unsigned)off) inc += t;
    }
    if ((tid & 31u) == 31u) warp_sums[tid >> 5] = inc;
    __syncthreads();
    if (tid < 32) {
        unsigned s = warp_sums[tid];
        #pragma unroll
        for (int off = 1; off < 32; off <<= 1) {
            unsigned t = __shfl_up_sync(~0u, s, off);
            if (tid >= (unsigned)off) s += t;
        }
        warp_sums[tid] = s;
    }
    __syncthreads();
    unsigned base = (tid >= 32u) ? warp_sums[(tid >> 5) - 1u] : 0u;
    return base + inc;
}

__global__ void scan1_kernel() {
    const unsigned tid = threadIdx.x;
    const unsigned g = blockIdx.x * SCAN_BLK + tid;
    const unsigned v = g_cell_count[g];
    const unsigned inc = block_incl_scan(v, tid);
    g_cell_start[g] = inc - v;
    if (tid == SCAN_BLK - 1) g_partials[blockIdx.x] = inc;
}

__global__ void scan2_kernel() {
    const unsigned tid = threadIdx.x;
    const unsigned a = g_partials[2 * tid];
    const unsigned b = g_partials[2 * tid + 1];
    const unsigned s = a + b;
    const unsigned inc = block_incl_scan(s, tid);
    const unsigned excl = inc - s;
    g_partials[2 * tid]     = excl;
    g_partials[2 * tid + 1] = excl + a;
}

// 4 pts/thread, float4 reads; block offset (scan3) folded in
__global__ void scatter_kernel(const float* __restrict__ x, int n) {
    const int j = blockIdx.x * blockDim.x + threadIdx.x;
    const int p0 = j * 4;
    if (p0 >= n) return;
    float c[12];
    if (p0 + 3 < n) {
        const float4* __restrict__ x4 = reinterpret_cast<const float4*>(x);
        const float4 a = x4[3 * j], b = x4[3 * j + 1], d = x4[3 * j + 2];
        c[0]=a.x; c[1]=a.y; c[2]=a.z; c[3]=a.w; c[4]=b.x; c[5]=b.y;
        c[6]=b.z; c[7]=b.w; c[8]=d.x; c[9]=d.y; c[10]=d.z; c[11]=d.w;
        #pragma unroll
        for (int k = 0; k < 4; k++) {
            const float xn0 = (c[3*k+0] + 1.0f) * 0.5f;
            const float xn1 = (c[3*k+1] + 1.0f) * 0.5f;
            const float xn2 = (c[3*k+2] + 1.0f) * 0.5f;
            const unsigned cc = cell_code(xn0, xn1, xn2);
            const unsigned pos = atomicAdd(&g_cell_start[cc], 1u) + g_partials[cc >> 10];
            g_pts[pos] = make_float4(xn0, xn1, xn2, __uint_as_float((unsigned)(p0 + k)));
        }
    } else {
        for (int k = 0; k < 4 && p0 + k < n; k++) {
            const int i = p0 + k;
            const float xn0 = (x[3*i+0] + 1.0f) * 0.5f;
            const float xn1 = (x[3*i+1] + 1.0f) * 0.5f;
            const float xn2 = (x[3*i+2] + 1.0f) * 0.5f;
            const unsigned cc = cell_code(xn0, xn1, xn2);
            const unsigned pos = atomicAdd(&g_cell_start[cc], 1u) + g_partials[cc >> 10];
            g_pts[pos] = make_float4(xn0, xn1, xn2, __uint_as_float((unsigned)i));
        }
    }
}

// ---- fused hash-encode + MLP ----
__global__ __launch_bounds__(128)
void field_fused_kernel(const float* __restrict__ table,
                        const float* __restrict__ W0,
                        const float* __restrict__ b0,
                        const float* __restrict__ W1,
                        const float* __restrict__ b1,
                        const float* __restrict__ Wout,
                        const float* __restrict__ bout,
                        float* __restrict__ out,
                        int n)
{
    __shared__ u64 sW0[35 * 32];
    __shared__ u64 sW1t[32 * 32];    // TRANSPOSED: sW1t[j*32 + i] = W1[i][j]
    __shared__ u64 sb0[32];
    __shared__ u64 sb1[32];
    __shared__ u64 sWout[32];
    __shared__ float sbout;

    const int tid = threadIdx.x;
    for (int i = tid; i < 35 * 32; i += blockDim.x) { float w = W0[i]; sW0[i] = pack2(w, w); }
    for (int i = tid; i < 32 * 32; i += blockDim.x) {
        const int r = i >> 5, cc = i & 31;           // W1[r][cc]
        float w = W1[i];
        sW1t[cc * 32 + r] = pack2(w, w);
    }
    if (tid < 32) {
        float v0 = b0[tid];   sb0[tid]   = pack2(v0, v0);
        float v1 = b1[tid];   sb1[tid]   = pack2(v1, v1);
        float vo = Wout[tid]; sWout[tid] = pack2(vo, vo);
    }
    if (tid == 0) sbout = bout[0];
    __syncthreads();

    // block-strided pairing over a 256-point chunk
    const int base = blockIdx.x * 256;
    const int iA = base + tid;
    if (iA >= n) return;
    int iB = base + 128 + tid;
    const bool hasB = iB < n;
    if (!hasB) iB = iA;

    const float4 ptA = g_pts[iA];
    const float4 ptB = g_pts[iB];
    const unsigned oiA = __float_as_uint(ptA.w);
    const unsigned oiB = __float_as_uint(ptB.w);

    const u64 xp0 = pack2(ptA.x, ptB.x);
    const u64 xp1 = pack2(ptA.y, ptB.y);
    const u64 xp2 = pack2(ptA.z, ptB.z);

    // ---- layer-0 accumulator (packed): bias + coords ----
    u64 h[HIDDEN];
    #pragma unroll
    for (int j = 0; j < HIDDEN; j++) {
        h[j] = ffma2(xp0, sW0[0 * 32 + j],
               ffma2(xp1, sW0[1 * 32 + j],
               ffma2(xp2, sW0[2 * 32 + j], sb0[j])));
    }

    // ---- hash-grid levels: lerp-tree trilinear, folded into h ----
    #pragma unroll 4
    for (int l = 0; l < NLEVELS; l++) {
        const float s = c_scales[l];
        const float2* __restrict__ tbl =
            reinterpret_cast<const float2*>(table) + (size_t)l * TSIZE;

        // point A
        const float pA0 = ptA.x * s, pA1 = ptA.y * s, pA2 = ptA.z * s;
        const float fA0 = floorf(pA0), fA1 = floorf(pA1), fA2 = floorf(pA2);
        const float wA0 = pA0 - fA0, wA1 = pA1 - fA1, wA2 = pA2 - fA2;
        const unsigned iA0 = (unsigned)fA0, iA1 = (unsigned)fA1, iA2 = (unsigned)fA2;
        const unsigned hxA0 = iA0,               hxA1 = iA0 + 1u;
        const unsigned hyA0 = iA1 * 2654435761u, hyA1 = (iA1 + 1u) * 2654435761u;
        const unsigned hzA0 = iA2 * 805459861u,  hzA1 = (iA2 + 1u) * 805459861u;
        // p index: bit0 = y corner, bit1 = z corner
        unsigned hyzA[4];
        hyzA[0] = hyA0 ^ hzA0; hyzA[1] = hyA1 ^ hzA0;
        hyzA[2] = hyA0 ^ hzA1; hyzA[3] = hyA1 ^ hzA1;

        // point B
        const float pB0 = ptB.x * s, pB1 = ptB.y * s, pB2 = ptB.z * s;
        const float fB0 = floorf(pB0), fB1 = floorf(pB1), fB2 = floorf(pB2);
        const float wB0 = pB0 - fB0, wB1 = pB1 - fB1, wB2 = pB2 - fB2;
        const unsigned iB0 = (unsigned)fB0, iB1 = (unsigned)fB1, iB2 = (unsigned)fB2;
        const unsigned hxB0 = iB0,               hxB1 = iB0 + 1u;
        const unsigned hyB0 = iB1 * 2654435761u, hyB1 = (iB1 + 1u) * 2654435761u;
        const unsigned hzB0 = iB2 * 805459861u,  hzB1 = (iB2 + 1u) * 805459861u;
        unsigned hyzB[4];
        hyzB[0] = hyB0 ^ hzB0; hyzB[1] = hyB1 ^ hzB0;
        hyzB[2] = hyB0 ^ hzB1; hyzB[3] = hyB1 ^ hzB1;

        // gathers (8 per point, unchanged addressing)
        float2 gA0[4], gA1[4], gB0[4], gB1[4];
        #pragma unroll
        for (int p = 0; p < 4; p++) {
            gA0[p] = __ldg(tbl + ((hxA0 ^ hyzA[p]) & (TSIZE - 1u)));
            gA1[p] = __ldg(tbl + ((hxA1 ^ hyzA[p]) & (TSIZE - 1u)));
            gB0[p] = __ldg(tbl + ((hxB0 ^ hyzB[p]) & (TSIZE - 1u)));
            gB1[p] = __ldg(tbl + ((hxB1 ^ hyzB[p]) & (TSIZE - 1u)));
        }

        // packed weights
        const u64 wp0 = pack2(wA0, wB0), op0 = pack2(1.0f - wA0, 1.0f - wB0);
        const u64 wp1 = pack2(wA1, wB1), op1 = pack2(1.0f - wA1, 1.0f - wB1);
        const u64 wp2 = pack2(wA2, wB2), op2 = pack2(1.0f - wA2, 1.0f - wB2);

        // x-stage lerps
        u64 gxX[4], gxY[4];
        #pragma unroll
        for (int p = 0; p < 4; p++) {
            gxX[p] = ffma2(wp0, pack2(gA1[p].x, gB1[p].x),
                     fmul2(op0, pack2(gA0[p].x, gB0[p].x)));
            gxY[p] = ffma2(wp0, pack2(gA1[p].y, gB1[p].y),
                     fmul2(op0, pack2(gA0[p].y, gB0[p].y)));
        }
        // y-stage
        const u64 gy0X = ffma2(wp1, gxX[1], fmul2(op1, gxX[0]));
        const u64 gy1X = ffma2(wp1, gxX[3], fmul2(op1, gxX[2]));
        const u64 gy0Y = ffma2(wp1, gxY[1], fmul2(op1, gxY[0]));
        const u64 gy1Y = ffma2(wp1, gxY[3], fmul2(op1, gxY[2]));
        // z-stage -> level features (packed A,B)
        const u64 a0 = ffma2(wp2, gy1X, fmul2(op2, gy0X));
        const u64 a1 = ffma2(wp2, gy1Y, fmul2(op2, gy0Y));

        // fold into h via 128-bit weight reads
        const ulonglong2* __restrict__ wr0 =
            reinterpret_cast<const ulonglong2*>(&sW0[(3 + 2 * l) * 32]);
        const ulonglong2* __restrict__ wr1 =
            reinterpret_cast<const ulonglong2*>(&sW0[(4 + 2 * l) * 32]);
        #pragma unroll
        for (int j2 = 0; j2 < 16; j2++) {
            const ulonglong2 w0v = wr0[j2];
            const ulonglong2 w1v = wr1[j2];
            h[2*j2]   = ffma2(a0, w0v.x, ffma2(a1, w1v.x, h[2*j2]));
            h[2*j2+1] = ffma2(a0, w0v.y, ffma2(a1, w1v.y, h[2*j2+1]));
        }
    }

    // ---- ELU on h ----
    #pragma unroll
    for (int j = 0; j < HIDDEN; j++) {
        float a, b;
        unpack2(h[j], a, b);
        h[j] = pack2(elu_fast(a), elu_fast(b));
    }

    // ---- layer 1 + output (transposed W1, 128-bit reads, no h2 array) ----
    u64 o = pack2(sbout, sbout);
    #pragma unroll 4
    for (int j = 0; j < HIDDEN; j++) {
        u64 t = sb1[j];
        const ulonglong2* __restrict__ wr =
            reinterpret_cast<const ulonglong2*>(&sW1t[j * 32]);
        #pragma unroll
        for (int i2 = 0; i2 < 16; i2++) {
            const ulonglong2 wv = wr[i2];
            t = ffma2(h[2*i2], wv.x, ffma2(h[2*i2+1], wv.y, t));
        }
        float a, b;
        unpack2(t, a, b);
        o = ffma2(pack2(elu_fast(a), elu_fast(b)), sWout[j], o);
    }

    float oA, oB;
    unpack2(o, oA, oB);
    out[oiA] = oA;
    if (hasB) out[oiB] = oB;
}

extern "C" void kernel_launch(void* const* d_in, const int* in_sizes, int n_in,
                              void* d_out, int out_size)
{
    const float* x     = (const float*)d_in[0];
    const float* table = (const float*)d_in[1];
    const float* W0    = (const float*)d_in[2];
    const float* b0    = (const float*)d_in[3];
    const float* W1    = (const float*)d_in[4];
    const float* b1    = (const float*)d_in[5];
    const float* Wout  = (const float*)d_in[6];
    const float* bout  = (const float*)d_in[7];
    float* out = (float*)d_out;

    const int n = in_sizes[0] / 3;
    const int nquad = (n + 3) / 4;

    zero_counts_kernel<<<NCELLS / 4 / 1024, 1024>>>();
    hist_kernel<<<(nquad + 255) / 256, 256>>>(x, n);
    scan1_kernel<<<NPART, SCAN_BLK>>>();
    scan2_kernel<<<1, SCAN_BLK>>>();
    scatter_kernel<<<(nquad + 255) / 256, 256>>>(x, n);

    const int nchunk = (n + 255) / 256;
    field_fused_kernel<<<nchunk, 128>>>(
        table, W0, b0, W1, b1, Wout, bout, out, n);
}